// round 1
// baseline (speedup 1.0000x reference)
#include <cuda_runtime.h>
#include <math.h>

#define H 192
#define W 192
#define HW (H*W)
#define NCH 24          // BT*C = 8*3
#define CROP 174
#define H0 9
#define W0 9
#define NPIX (CROP*CROP)        // 30276
#define NCAND 75
#define SPLIT 8
#define NBT 8

__device__ float g_imgT[HW * NCH];            // [y][x][ch]
__device__ float g_refT[NPIX * NCH];          // [i][j][ch]
__device__ float g_partial[NCAND * SPLIT * NBT];

// ---------------------------------------------------------------------------
// Transpose matrix [24][192][192] -> [192*192][24]  (coalesced writes)
// ---------------------------------------------------------------------------
__global__ void transpose_img_kernel(const float* __restrict__ in) {
    int k = blockIdx.x * blockDim.x + threadIdx.x;
    if (k < HW * NCH) {
        int ch = k % NCH;
        int p  = k / NCH;
        g_imgT[k] = in[ch * HW + p];
    }
}

// Transpose ref crop [24][192][192] -> [174*174][24]
__global__ void transpose_ref_kernel(const float* __restrict__ in) {
    int k = blockIdx.x * blockDim.x + threadIdx.x;
    if (k < NPIX * NCH) {
        int ch = k % NCH;
        int p  = k / NCH;
        int i  = p / CROP;
        int j  = p % CROP;
        g_refT[k] = in[ch * HW + (i + H0) * W + (j + W0)];
    }
}

// ---------------------------------------------------------------------------
// Main SAD kernel.
// Block = 192 threads = 32 pixel-lanes x 6 channel-groups (4 ch each).
// Grid  = (NCAND, SPLIT). Each block accumulates partial SAD per bt.
// ---------------------------------------------------------------------------
__global__ __launch_bounds__(192) void sad_kernel() {
    const int n = blockIdx.x;
    const int s = blockIdx.y;
    const int t = threadIdx.x;
    const int g = t % 6;          // channel group: ch = 4g .. 4g+3
    const int lane_px = t / 6;    // 0..31

    // Candidate parameters: n = i0*15 + i1*3 + i2  (DIMS 5,5,3,1)
    const int i0 = n / 15;
    const int i1 = (n / 3) % 5;
    const int i2 = n % 3;
    const float ash = (float)(2 - i0);                 // -SHIFT_H[i0]
    const float asw = (float)(2 - i1);                 // -SHIFT_W[i1]
    const float arot = -(float)(i2 - 1) * (float)(M_PI / 180.0);
    const float cr = cosf(arot);
    const float sr = sinf(arot);

    // bt mapping of this thread's 4 channels: spans exactly bt_lo, bt_lo+1
    const int bt_lo  = (4 * g) / 3;
    const int cnt_lo = 3 - (4 * g) % 3;   // how many of the 4 ch belong to bt_lo

    float acc0 = 0.0f;   // goes to bt_lo
    float acc1 = 0.0f;   // goes to bt_lo + 1

    const int chunk = (NPIX + SPLIT - 1) / SPLIT;
    const int p_begin = s * chunk;
    const int p_end   = min(p_begin + chunk, NPIX);

    for (int p = p_begin + lane_px; p < p_end; p += 32) {
        const int i = p / CROP;
        const int j = p % CROP;

        // --- grid coords (mirror the reference op sequence in fp32) ---
        const float xx = (float)(W0 + j);
        const float yy = (float)(H0 + i);
        const float aw = xx + asw;            // asc == 1
        const float ah = yy + ash;
        const float awc = aw - 95.5f;         // cx = (W-1)/2
        const float ahc = ah - 95.5f;
        const float awr = cr * awc - sr * ahc;
        const float ahr = sr * awc + cr * ahc;
        const float gx = awr * (1.0f / 95.5f);
        const float gy = ahr * (1.0f / 95.5f);
        const float x = ((gx + 1.0f) * (float)W - 1.0f) * 0.5f;
        const float y = ((gy + 1.0f) * (float)H - 1.0f) * 0.5f;

        // --- bilinear setup ---
        const float x0f = floorf(x);
        const float y0f = floorf(y);
        const float wx = x - x0f;
        const float wy = y - y0f;
        const int x0 = (int)x0f;
        const int y0 = (int)y0f;
        const int x1 = x0 + 1;
        const int y1 = y0 + 1;

        float wA = (1.0f - wx) * (1.0f - wy);   // (x0, y0)
        float wB = wx * (1.0f - wy);            // (x1, y0)
        float wC = (1.0f - wx) * wy;            // (x0, y1)
        float wD = wx * wy;                     // (x1, y1)

        const bool vx0 = (x0 >= 0) && (x0 < W);
        const bool vx1 = (x1 >= 0) && (x1 < W);
        const bool vy0 = (y0 >= 0) && (y0 < H);
        const bool vy1 = (y1 >= 0) && (y1 < H);
        wA *= (vx0 && vy0) ? 1.0f : 0.0f;
        wB *= (vx1 && vy0) ? 1.0f : 0.0f;
        wC *= (vx0 && vy1) ? 1.0f : 0.0f;
        wD *= (vx1 && vy1) ? 1.0f : 0.0f;

        const int xc0 = min(max(x0, 0), W - 1);
        const int xc1 = min(max(x1, 0), W - 1);
        const int yc0 = min(max(y0, 0), H - 1);
        const int yc1 = min(max(y1, 0), H - 1);

        const int row0 = yc0 * W;
        const int row1 = yc1 * W;
        const int oA = (row0 + xc0) * NCH + 4 * g;
        const int oB = (row0 + xc1) * NCH + 4 * g;
        const int oC = (row1 + xc0) * NCH + 4 * g;
        const int oD = (row1 + xc1) * NCH + 4 * g;

        const float4 vA = *(const float4*)(g_imgT + oA);
        const float4 vB = *(const float4*)(g_imgT + oB);
        const float4 vC = *(const float4*)(g_imgT + oC);
        const float4 vD = *(const float4*)(g_imgT + oD);
        const float4 rf = *(const float4*)(g_refT + p * NCH + 4 * g);

        const float m0 = fabsf(wA * vA.x + wB * vB.x + wC * vC.x + wD * vD.x - rf.x);
        const float m1 = fabsf(wA * vA.y + wB * vB.y + wC * vC.y + wD * vD.y - rf.y);
        const float m2 = fabsf(wA * vA.z + wB * vB.z + wC * vC.z + wD * vD.z - rf.z);
        const float m3 = fabsf(wA * vA.w + wB * vB.w + wC * vC.w + wD * vD.w - rf.w);

        // ch 4g+k belongs to bt_lo iff k < cnt_lo  (cnt_lo in {1,2,3})
        acc0 += m0;                                     // k=0 always lo
        if (cnt_lo > 1) acc0 += m1; else acc1 += m1;
        if (cnt_lo > 2) acc0 += m2; else acc1 += m2;
        acc1 += m3;                                     // k=3 always hi
    }

    __shared__ float sadS[NBT];
    if (t < NBT) sadS[t] = 0.0f;
    __syncthreads();
    atomicAdd(&sadS[bt_lo], acc0);
    atomicAdd(&sadS[bt_lo + 1], acc1);
    __syncthreads();
    if (t < NBT) {
        g_partial[(n * SPLIT + s) * NBT + t] = sadS[t];
    }
}

// ---------------------------------------------------------------------------
// Finalize: fixed-order sum over splits, mean, argmin + unravel_index.
// Output layout: out[0..599] = sad[n][bt] (row-major),
//                out[600 + d*8 + bt] = min_idx[d][bt] as float
// ---------------------------------------------------------------------------
__global__ void finalize_kernel(float* __restrict__ out, int out_size) {
    __shared__ float sadSh[NCAND * NBT];
    const int t = threadIdx.x;
    if (t < NCAND * NBT) {
        const int n = t / NBT;
        const int bt = t % NBT;
        float ssum = 0.0f;
        #pragma unroll
        for (int k = 0; k < SPLIT; k++)
            ssum += g_partial[(n * SPLIT + k) * NBT + bt];
        ssum *= (1.0f / (float)(3 * NPIX));   // mean over (C, CROP_H, CROP_W)
        sadSh[t] = ssum;
        out[t] = ssum;
    }
    __syncthreads();
    if (t < NBT && out_size >= NCAND * NBT + 4 * NBT) {
        const int bt = t;
        float best = sadSh[bt];
        int bn = 0;
        for (int n = 1; n < NCAND; n++) {
            const float v = sadSh[n * NBT + bt];
            if (v < best) { best = v; bn = n; }   // first-min, matches argmin
        }
        const int i0 = bn / 15;
        const int i1 = (bn / 3) % 5;
        const int i2 = bn % 3;
        out[NCAND * NBT + 0 * NBT + bt] = (float)i0;
        out[NCAND * NBT + 1 * NBT + bt] = (float)i1;
        out[NCAND * NBT + 2 * NBT + bt] = (float)i2;
        out[NCAND * NBT + 3 * NBT + bt] = 0.0f;
    }
}

extern "C" void kernel_launch(void* const* d_in, const int* in_sizes, int n_in,
                              void* d_out, int out_size) {
    const float* matrix = (const float*)d_in[0];
    const float* refm   = (const float*)d_in[1];

    transpose_img_kernel<<<(HW * NCH + 255) / 256, 256>>>(matrix);
    transpose_ref_kernel<<<(NPIX * NCH + 255) / 256, 256>>>(refm);

    dim3 grid(NCAND, SPLIT);
    sad_kernel<<<grid, 192>>>();

    finalize_kernel<<<1, 640>>>((float*)d_out, out_size);
}

// round 2
// speedup vs baseline: 1.2857x; 1.2857x over previous
#include <cuda_runtime.h>
#include <math.h>

#define H 192
#define W 192
#define HW (H*W)
#define NCH 24          // BT*C = 8*3
#define CROP 174
#define H0 9
#define W0 9
#define NPIX (CROP*CROP)        // 30276
#define NCAND 75
#define SPLIT 16
#define NBT 8

__device__ float g_imgT[HW * NCH];            // [y][x][ch]
__device__ float g_refT[NPIX * NCH];          // [i][j][ch]
__device__ float g_partial[NCAND * SPLIT * NBT];

// ---------------------------------------------------------------------------
// Transpose matrix [24][192][192] -> [192*192][24]  (coalesced writes)
// ---------------------------------------------------------------------------
__global__ void transpose_img_kernel(const float* __restrict__ in) {
    int k = blockIdx.x * blockDim.x + threadIdx.x;
    if (k < HW * NCH) {
        int ch = k % NCH;
        int p  = k / NCH;
        g_imgT[k] = in[ch * HW + p];
    }
}

// Transpose ref crop [24][192][192] -> [174*174][24]
__global__ void transpose_ref_kernel(const float* __restrict__ in) {
    int k = blockIdx.x * blockDim.x + threadIdx.x;
    if (k < NPIX * NCH) {
        int ch = k % NCH;
        int p  = k / NCH;
        int i  = p / CROP;
        int j  = p % CROP;
        g_refT[k] = in[ch * HW + (i + H0) * W + (j + W0)];
    }
}

// ---------------------------------------------------------------------------
// Main SAD kernel.
// Block = 192 threads = 32 pixel-lanes x 6 channel-groups (4 ch each).
// Grid  = (NCAND, SPLIT).
// Coordinates are affine in (i,j); all corners provably in-bounds (margin 9px
// vs max displacement < 4.3px), so no masks/clamps.
// ---------------------------------------------------------------------------
__global__ __launch_bounds__(192) void sad_kernel() {
    const int n = blockIdx.x;
    const int s = blockIdx.y;
    const int t = threadIdx.x;
    const int g = t % 6;          // channel group: ch = 4g .. 4g+3
    const int lane_px = t / 6;    // 0..31
    const int g4 = 4 * g;

    // Candidate parameters: n = i0*15 + i1*3 + i2  (DIMS 5,5,3,1)
    const int i0 = n / 15;
    const int i1 = (n / 3) % 5;
    const int i2 = n % 3;
    const float ash = (float)(2 - i0);                 // -SHIFT_H[i0]
    const float asw = (float)(2 - i1);                 // -SHIFT_W[i1]
    const float arot = -(float)(i2 - 1) * (float)(M_PI / 180.0);
    const float cr = cosf(arot);
    const float sr = sinf(arot);

    // Affine map: x = ax*j + bx*i + cx0 ; y = ay*j + by*i + cy0
    // derived from the reference chain with asc = 1, cx = cy = 95.5,
    // x = awr*(96/95.5) + 95.5, awr = cr*(j+W0+asw-95.5) - sr*(i+H0+ash-95.5)
    const float SC = 96.0f / 95.5f;
    const float u0 = asw - 86.5f;   // W0 + asw - 95.5
    const float v0 = ash - 86.5f;   // H0 + ash - 95.5
    const float ax = SC * cr;
    const float bx = -SC * sr;
    const float cx0 = SC * (cr * u0 - sr * v0) + 95.5f;
    const float ay = SC * sr;
    const float by = SC * cr;
    const float cy0 = SC * (sr * u0 + cr * v0) + 95.5f;

    // bt mapping of this thread's 4 channels: spans exactly bt_lo, bt_lo+1
    const int bt_lo  = (4 * g) / 3;
    const int cnt_lo = 3 - (4 * g) % 3;   // how many of the 4 ch belong to bt_lo

    float acc0 = 0.0f;   // goes to bt_lo
    float acc1 = 0.0f;   // goes to bt_lo + 1

    const int chunk = (NPIX + SPLIT - 1) / SPLIT;
    const int p_begin = s * chunk;
    const int p_end   = min(p_begin + chunk, NPIX);

    #pragma unroll 2
    for (int p = p_begin + lane_px; p < p_end; p += 32) {
        const int i = p / CROP;
        const int j = p - i * CROP;
        const float jf = (float)j;
        const float fi = (float)i;

        const float x = fmaf(ax, jf, fmaf(bx, fi, cx0));
        const float y = fmaf(ay, jf, fmaf(by, fi, cy0));

        const float x0f = floorf(x);
        const float y0f = floorf(y);
        const float wx = x - x0f;
        const float wy = y - y0f;
        const int x0 = (int)x0f;
        const int y0 = (int)y0f;

        const float wx1 = 1.0f - wx;
        const float wy1 = 1.0f - wy;
        const float wA = wx1 * wy1;
        const float wB = wx  * wy1;
        const float wC = wx1 * wy;
        const float wD = wx  * wy;

        const int oA = (y0 * W + x0) * NCH + g4;

        const float4 vA = *(const float4*)(g_imgT + oA);
        const float4 vB = *(const float4*)(g_imgT + oA + NCH);
        const float4 vC = *(const float4*)(g_imgT + oA + W * NCH);
        const float4 vD = *(const float4*)(g_imgT + oA + W * NCH + NCH);
        const float4 rf = *(const float4*)(g_refT + p * NCH + g4);

        float t0 = wA * vA.x; t0 = fmaf(wB, vB.x, t0); t0 = fmaf(wC, vC.x, t0); t0 = fmaf(wD, vD.x, t0);
        float t1 = wA * vA.y; t1 = fmaf(wB, vB.y, t1); t1 = fmaf(wC, vC.y, t1); t1 = fmaf(wD, vD.y, t1);
        float t2 = wA * vA.z; t2 = fmaf(wB, vB.z, t2); t2 = fmaf(wC, vC.z, t2); t2 = fmaf(wD, vD.z, t2);
        float t3 = wA * vA.w; t3 = fmaf(wB, vB.w, t3); t3 = fmaf(wC, vC.w, t3); t3 = fmaf(wD, vD.w, t3);

        const float m0 = fabsf(t0 - rf.x);
        const float m1 = fabsf(t1 - rf.y);
        const float m2 = fabsf(t2 - rf.z);
        const float m3 = fabsf(t3 - rf.w);

        // ch 4g+k belongs to bt_lo iff k < cnt_lo  (cnt_lo in {1,2,3})
        acc0 += m0;                                     // k=0 always lo
        if (cnt_lo > 1) acc0 += m1; else acc1 += m1;
        if (cnt_lo > 2) acc0 += m2; else acc1 += m2;
        acc1 += m3;                                     // k=3 always hi
    }

    __shared__ float sadS[NBT];
    if (t < NBT) sadS[t] = 0.0f;
    __syncthreads();
    atomicAdd(&sadS[bt_lo], acc0);
    atomicAdd(&sadS[bt_lo + 1], acc1);
    __syncthreads();
    if (t < NBT) {
        g_partial[(n * SPLIT + s) * NBT + t] = sadS[t];
    }
}

// ---------------------------------------------------------------------------
// Finalize: fixed-order sum over splits, mean, argmin + unravel_index.
// Output layout: out[0..599] = sad[n][bt] (row-major),
//                out[600 + d*8 + bt] = min_idx[d][bt] as float
// ---------------------------------------------------------------------------
__global__ void finalize_kernel(float* __restrict__ out, int out_size) {
    __shared__ float sadSh[NCAND * NBT];
    const int t = threadIdx.x;
    if (t < NCAND * NBT) {
        const int n = t / NBT;
        const int bt = t % NBT;
        float ssum = 0.0f;
        #pragma unroll
        for (int k = 0; k < SPLIT; k++)
            ssum += g_partial[(n * SPLIT + k) * NBT + bt];
        ssum *= (1.0f / (float)(3 * NPIX));   // mean over (C, CROP_H, CROP_W)
        sadSh[t] = ssum;
        out[t] = ssum;
    }
    __syncthreads();
    if (t < NBT && out_size >= NCAND * NBT + 4 * NBT) {
        const int bt = t;
        float best = sadSh[bt];
        int bn = 0;
        for (int n = 1; n < NCAND; n++) {
            const float v = sadSh[n * NBT + bt];
            if (v < best) { best = v; bn = n; }   // first-min, matches argmin
        }
        const int i0 = bn / 15;
        const int i1 = (bn / 3) % 5;
        const int i2 = bn % 3;
        out[NCAND * NBT + 0 * NBT + bt] = (float)i0;
        out[NCAND * NBT + 1 * NBT + bt] = (float)i1;
        out[NCAND * NBT + 2 * NBT + bt] = (float)i2;
        out[NCAND * NBT + 3 * NBT + bt] = 0.0f;
    }
}

extern "C" void kernel_launch(void* const* d_in, const int* in_sizes, int n_in,
                              void* d_out, int out_size) {
    const float* matrix = (const float*)d_in[0];
    const float* refm   = (const float*)d_in[1];

    transpose_img_kernel<<<(HW * NCH + 255) / 256, 256>>>(matrix);
    transpose_ref_kernel<<<(NPIX * NCH + 255) / 256, 256>>>(refm);

    dim3 grid(NCAND, SPLIT);
    sad_kernel<<<grid, 192>>>();

    finalize_kernel<<<1, 640>>>((float*)d_out, out_size);
}

// round 4
// speedup vs baseline: 2.1305x; 1.6571x over previous
#include <cuda_runtime.h>
#include <cuda_fp16.h>
#include <math.h>

#define H 192
#define W 192
#define HW (H*W)
#define NCH 24          // BT*C = 8*3
#define CROP 174
#define H0 9
#define W0 9
#define NPIX (CROP*CROP)        // 30276
#define NCAND 75
#define SPLIT 16
#define NBT 8
#define NLANES 64       // pixel lanes per block
#define NTHR 192        // NLANES * 3 groups

__device__ __half g_imgT[HW * NCH];           // [y][x][ch] fp16
__device__ __half g_refT[NPIX * NCH];         // [i][j][ch] fp16
__device__ float  g_partial[NCAND * SPLIT * NBT];

// ---------------------------------------------------------------------------
// Convert+transpose: matrix [24][192][192] f32 -> g_imgT [192*192][24] half,
// and ref crop -> g_refT [174*174][24] half. One kernel.
// ---------------------------------------------------------------------------
__global__ void convert_kernel(const float* __restrict__ img,
                               const float* __restrict__ ref) {
    const int k = blockIdx.x * blockDim.x + threadIdx.x;
    if (k < HW * NCH) {
        const int ch = k % NCH;
        const int p  = k / NCH;
        g_imgT[k] = __float2half(img[ch * HW + p]);
    }
    if (k < NPIX * NCH) {
        const int ch = k % NCH;
        const int p  = k / NCH;
        const int i  = p / CROP;
        const int j  = p - i * CROP;
        g_refT[k] = __float2half(ref[ch * HW + (i + H0) * W + (j + W0)]);
    }
}

// ---------------------------------------------------------------------------
// Main SAD kernel (fp16 data, half2 math).
// Block = 192 threads = 64 pixel-lanes x 3 channel-groups (8 ch each).
// Grid  = (NCAND, SPLIT). All corners provably in-bounds (9px margin vs
// <4.3px max displacement) -> no masks/clamps. Coordinates affine in (i,j).
// ---------------------------------------------------------------------------
__global__ __launch_bounds__(NTHR, 8) void sad_kernel() {
    const int n = blockIdx.x;
    const int s = blockIdx.y;
    const int t = threadIdx.x;
    const int g = t % 3;          // channel group: ch = 8g .. 8g+7
    const int lane_px = t / 3;    // 0..63
    const int g8 = 8 * g;

    // Candidate parameters: n = i0*15 + i1*3 + i2  (DIMS 5,5,3,1)
    const int i0 = n / 15;
    const int i1 = (n / 3) % 5;
    const int i2 = n % 3;
    const float ash = (float)(2 - i0);
    const float asw = (float)(2 - i1);
    const float arot = -(float)(i2 - 1) * (float)(M_PI / 180.0);
    const float cr = cosf(arot);
    const float sr = sinf(arot);

    // Affine map: x = ax*j + bx*i + cx0 ; y = ay*j + by*i + cy0
    const float SC = 96.0f / 95.5f;
    const float u0 = asw - 86.5f;
    const float v0 = ash - 86.5f;
    const float ax = SC * cr;
    const float bx = -SC * sr;
    const float cx0 = SC * (cr * u0 - sr * v0) + 95.5f;
    const float ay = SC * sr;
    const float by = SC * cr;
    const float cy0 = SC * (sr * u0 + cr * v0) + 95.5f;

    // 8 per-channel fp32 accumulators; bt routing deferred to block end.
    float acc[8];
    #pragma unroll
    for (int k = 0; k < 8; k++) acc[k] = 0.0f;

    const int chunk = (NPIX + SPLIT - 1) / SPLIT;
    const int p_begin = s * chunk;
    const int p_end   = min(p_begin + chunk, NPIX);

    #pragma unroll 2
    for (int p = p_begin + lane_px; p < p_end; p += NLANES) {
        const int i = p / CROP;
        const int j = p - i * CROP;

        const float x = fmaf(ax, (float)j, fmaf(bx, (float)i, cx0));
        const float y = fmaf(ay, (float)j, fmaf(by, (float)i, cy0));

        const float x0f = floorf(x);
        const float y0f = floorf(y);
        const float wx = x - x0f;
        const float wy = y - y0f;
        const int x0 = (int)x0f;
        const int y0 = (int)y0f;

        const float wx1 = 1.0f - wx;
        const float wy1 = 1.0f - wy;
        const __half2 wA2 = __float2half2_rn(wx1 * wy1);
        const __half2 wB2 = __float2half2_rn(wx  * wy1);
        const __half2 wC2 = __float2half2_rn(wx1 * wy);
        const __half2 wD2 = __float2half2_rn(wx  * wy);

        const int base = (y0 * W + x0) * NCH + g8;   // half elements, 16B-aligned

        const float4 fA = *(const float4*)(g_imgT + base);
        const float4 fB = *(const float4*)(g_imgT + base + NCH);
        const float4 fC = *(const float4*)(g_imgT + base + W * NCH);
        const float4 fD = *(const float4*)(g_imgT + base + W * NCH + NCH);
        const float4 fR = *(const float4*)(g_refT + p * NCH + g8);

        const __half2* hA = (const __half2*)&fA;
        const __half2* hB = (const __half2*)&fB;
        const __half2* hC = (const __half2*)&fC;
        const __half2* hD = (const __half2*)&fD;
        const __half2* hR = (const __half2*)&fR;

        #pragma unroll
        for (int u = 0; u < 4; u++) {
            __half2 tv = __hmul2(wA2, hA[u]);
            tv = __hfma2(wB2, hB[u], tv);
            tv = __hfma2(wC2, hC[u], tv);
            tv = __hfma2(wD2, hD[u], tv);
            const __half2 d = __habs2(__hsub2(tv, hR[u]));
            const float2 df = __half22float2(d);
            acc[2 * u]     += df.x;
            acc[2 * u + 1] += df.y;
        }
    }

    // ---- Deterministic block reduction: acc[k] of thread t belongs to
    //      channel c = 8*g + k, bt = c / 3. Two-stage fixed-order tree. ----
    __shared__ float sc[8 * NTHR];     // sc[k*NTHR + t]
    __shared__ float s2[NBT * 24];
    #pragma unroll
    for (int k = 0; k < 8; k++) sc[k * NTHR + t] = acc[k];
    __syncthreads();

    // Stage 1: 192 threads: u -> (bt = u/24, i = u%24); channel c = bt*3 + i/8;
    // source group gs = c/8, k = c%8; sum 8 source threads t' = gs + 3*(m8*8+j).
    {
        const int bt = t / 24;
        const int ii = t % 24;
        const int c  = bt * 3 + ii / 8;
        const int gs = c / 8;
        const int k  = c % 8;
        const int m8 = ii % 8;
        float ssum = 0.0f;
        #pragma unroll
        for (int jj = 0; jj < 8; jj++)
            ssum += sc[k * NTHR + gs + 3 * (m8 * 8 + jj)];
        s2[bt * 24 + ii] = ssum;
    }
    __syncthreads();

    if (t < NBT) {
        float ssum = 0.0f;
        #pragma unroll
        for (int ii = 0; ii < 24; ii++)
            ssum += s2[t * 24 + ii];
        g_partial[(n * SPLIT + s) * NBT + t] = ssum;
    }
}

// ---------------------------------------------------------------------------
// Finalize: fixed-order sum over splits, mean, argmin + unravel_index.
// ---------------------------------------------------------------------------
__global__ void finalize_kernel(float* __restrict__ out, int out_size) {
    __shared__ float sadSh[NCAND * NBT];
    const int t = threadIdx.x;
    if (t < NCAND * NBT) {
        const int n = t / NBT;
        const int bt = t % NBT;
        float ssum = 0.0f;
        #pragma unroll
        for (int k = 0; k < SPLIT; k++)
            ssum += g_partial[(n * SPLIT + k) * NBT + bt];
        ssum *= (1.0f / (float)(3 * NPIX));
        sadSh[t] = ssum;
        out[t] = ssum;
    }
    __syncthreads();
    if (t < NBT && out_size >= NCAND * NBT + 4 * NBT) {
        const int bt = t;
        float best = sadSh[bt];
        int bn = 0;
        for (int n = 1; n < NCAND; n++) {
            const float v = sadSh[n * NBT + bt];
            if (v < best) { best = v; bn = n; }
        }
        const int i0 = bn / 15;
        const int i1 = (bn / 3) % 5;
        const int i2 = bn % 3;
        out[NCAND * NBT + 0 * NBT + bt] = (float)i0;
        out[NCAND * NBT + 1 * NBT + bt] = (float)i1;
        out[NCAND * NBT + 2 * NBT + bt] = (float)i2;
        out[NCAND * NBT + 3 * NBT + bt] = 0.0f;
    }
}

extern "C" void kernel_launch(void* const* d_in, const int* in_sizes, int n_in,
                              void* d_out, int out_size) {
    const float* matrix = (const float*)d_in[0];
    const float* refm   = (const float*)d_in[1];

    convert_kernel<<<(HW * NCH + 255) / 256, 256>>>(matrix, refm);

    dim3 grid(NCAND, SPLIT);
    sad_kernel<<<grid, NTHR>>>();

    finalize_kernel<<<1, 640>>>((float*)d_out, out_size);
}

// round 5
// speedup vs baseline: 2.2164x; 1.0403x over previous
#include <cuda_runtime.h>
#include <cuda_fp16.h>
#include <math.h>

#define H 192
#define W 192
#define HW (H*W)
#define NCH 24          // BT*C = 8*3
#define CROP 174
#define H0 9
#define W0 9
#define NPIX (CROP*CROP)        // 30276
#define NCAND 75
#define SPLIT 16
#define NBT 8
#define NLANES 64       // pixel lanes per block
#define NTHR 192        // NLANES * 3 groups
#define IMG_BLKS (HW / 256)                 // 144
#define REF_BLKS ((NPIX + 255) / 256)       // 119

__device__ __half g_imgT[HW * NCH];           // [y][x][ch] fp16
__device__ __half g_refT[NPIX * NCH];         // [i][j][ch] fp16
__device__ float  g_partial[NCAND * SPLIT * NBT];
__device__ int    g_count;

// ---------------------------------------------------------------------------
// Convert+transpose via smem tiles: coalesced channel-row reads, coalesced
// 4B record writes. Blocks [0,144) do the image, [144,263) the ref crop.
// Also resets the completion counter used by the fused finalize.
// ---------------------------------------------------------------------------
__global__ __launch_bounds__(256) void convert_kernel(const float* __restrict__ img,
                                                      const float* __restrict__ ref) {
    __shared__ __half s[256][26];   // stride 26 halves = 52 B (4-aligned)
    const int b = blockIdx.x;
    const int tid = threadIdx.x;
    if (b == 0 && tid == 0) g_count = 0;

    if (b < IMG_BLKS) {
        const int p0 = b * 256;
        #pragma unroll
        for (int ch = 0; ch < NCH; ch++)
            s[tid][ch] = __float2half(img[ch * HW + p0 + tid]);
        __syncthreads();
        unsigned int* out32 = (unsigned int*)g_imgT;
        #pragma unroll
        for (int w = 0; w < 12; w++) {
            const int idx = w * 256 + tid;       // 0..3071
            const int px = idx / 12;
            const int u  = idx - px * 12;
            out32[p0 * 12 + idx] = *(const unsigned int*)&s[px][2 * u];
        }
    } else {
        const int p0 = (b - IMG_BLKS) * 256;
        const int p = p0 + tid;
        const bool valid = (p < NPIX);
        const int i = p / CROP;
        const int j = p - i * CROP;
        const int src = (i + H0) * W + (j + W0);
        #pragma unroll
        for (int ch = 0; ch < NCH; ch++)
            s[tid][ch] = valid ? __float2half(ref[ch * HW + src]) : __half(0.0f);
        __syncthreads();
        const int total32 = (min(256, NPIX - p0)) * 12;
        unsigned int* out32 = (unsigned int*)g_refT;
        #pragma unroll
        for (int w = 0; w < 12; w++) {
            const int idx = w * 256 + tid;
            if (idx < total32) {
                const int px = idx / 12;
                const int u  = idx - px * 12;
                out32[p0 * 12 + idx] = *(const unsigned int*)&s[px][2 * u];
            }
        }
    }
}

// ---------------------------------------------------------------------------
// Main SAD kernel (fp16 data, half2 math) + fused finalize (last block).
// Block = 192 threads = 64 pixel-lanes x 3 channel-groups (8 ch each).
// Grid  = (NCAND, SPLIT). All corners provably in-bounds (9px margin vs
// <4.3px max displacement) -> no masks/clamps. Coordinates affine in (i,j).
// ---------------------------------------------------------------------------
__global__ __launch_bounds__(NTHR, 8) void sad_kernel(float* __restrict__ out,
                                                      int out_size) {
    const int n = blockIdx.x;
    const int s = blockIdx.y;
    const int t = threadIdx.x;
    const int g = t % 3;          // channel group: ch = 8g .. 8g+7
    const int lane_px = t / 3;    // 0..63
    const int g8 = 8 * g;

    // Candidate parameters: n = i0*15 + i1*3 + i2  (DIMS 5,5,3,1)
    const int i0 = n / 15;
    const int i1 = (n / 3) % 5;
    const int i2 = n % 3;
    const float ash = (float)(2 - i0);
    const float asw = (float)(2 - i1);
    const float arot = -(float)(i2 - 1) * (float)(M_PI / 180.0);
    const float cr = cosf(arot);
    const float sr = sinf(arot);

    // Affine map: x = ax*j + bx*i + cx0 ; y = ay*j + by*i + cy0
    const float SC = 96.0f / 95.5f;
    const float u0 = asw - 86.5f;
    const float v0 = ash - 86.5f;
    const float ax = SC * cr;
    const float bx = -SC * sr;
    const float cx0 = SC * (cr * u0 - sr * v0) + 95.5f;
    const float ay = SC * sr;
    const float by = SC * cr;
    const float cy0 = SC * (sr * u0 + cr * v0) + 95.5f;

    float acc[8];
    #pragma unroll
    for (int k = 0; k < 8; k++) acc[k] = 0.0f;

    const int chunk = (NPIX + SPLIT - 1) / SPLIT;
    const int p_begin = s * chunk;
    const int p_end   = min(p_begin + chunk, NPIX);

    // Incremental (i, j): stride 64 < CROP so at most one row wrap per step.
    int p = p_begin + lane_px;
    int pi = p / CROP;
    int pj = p - pi * CROP;

    #pragma unroll 2
    for (; p < p_end; p += NLANES) {
        const float x = fmaf(ax, (float)pj, fmaf(bx, (float)pi, cx0));
        const float y = fmaf(ay, (float)pj, fmaf(by, (float)pi, cy0));

        const float x0f = floorf(x);
        const float y0f = floorf(y);
        const float wx = x - x0f;
        const float wy = y - y0f;
        const int x0 = (int)x0f;
        const int y0 = (int)y0f;

        const float wx1 = 1.0f - wx;
        const float wy1 = 1.0f - wy;
        const __half2 wA2 = __float2half2_rn(wx1 * wy1);
        const __half2 wB2 = __float2half2_rn(wx  * wy1);
        const __half2 wC2 = __float2half2_rn(wx1 * wy);
        const __half2 wD2 = __float2half2_rn(wx  * wy);

        const int base = (y0 * W + x0) * NCH + g8;

        const float4 fA = *(const float4*)(g_imgT + base);
        const float4 fB = *(const float4*)(g_imgT + base + NCH);
        const float4 fC = *(const float4*)(g_imgT + base + W * NCH);
        const float4 fD = *(const float4*)(g_imgT + base + W * NCH + NCH);
        const float4 fR = *(const float4*)(g_refT + p * NCH + g8);

        const __half2* hA = (const __half2*)&fA;
        const __half2* hB = (const __half2*)&fB;
        const __half2* hC = (const __half2*)&fC;
        const __half2* hD = (const __half2*)&fD;
        const __half2* hR = (const __half2*)&fR;

        #pragma unroll
        for (int u = 0; u < 4; u++) {
            __half2 tv = __hmul2(wA2, hA[u]);
            tv = __hfma2(wB2, hB[u], tv);
            tv = __hfma2(wC2, hC[u], tv);
            tv = __hfma2(wD2, hD[u], tv);
            const __half2 d = __habs2(__hsub2(tv, hR[u]));
            const float2 df = __half22float2(d);
            acc[2 * u]     += df.x;
            acc[2 * u + 1] += df.y;
        }

        pj += NLANES;
        if (pj >= CROP) { pj -= CROP; pi += 1; }
    }

    // ---- Deterministic block reduction ----
    __shared__ float sc[8 * NTHR];
    __shared__ float s2[NBT * 24];
    #pragma unroll
    for (int k = 0; k < 8; k++) sc[k * NTHR + t] = acc[k];
    __syncthreads();
    {
        const int bt = t / 24;
        const int ii = t % 24;
        const int c  = bt * 3 + ii / 8;
        const int gs = c / 8;
        const int k  = c % 8;
        const int m8 = ii % 8;
        float ssum = 0.0f;
        #pragma unroll
        for (int jj = 0; jj < 8; jj++)
            ssum += sc[k * NTHR + gs + 3 * (m8 * 8 + jj)];
        s2[bt * 24 + ii] = ssum;
    }
    __syncthreads();
    if (t < NBT) {
        float ssum = 0.0f;
        #pragma unroll
        for (int ii = 0; ii < 24; ii++)
            ssum += s2[t * 24 + ii];
        g_partial[(n * SPLIT + s) * NBT + t] = ssum;
    }

    // ---- Fused finalize: last block to finish does the reduction ----
    __shared__ int isLast;
    __threadfence();
    __syncthreads();
    if (t == 0) {
        const int old = atomicAdd(&g_count, 1);
        isLast = (old == NCAND * SPLIT - 1) ? 1 : 0;
    }
    __syncthreads();
    if (isLast) {
        __shared__ float sadSh[NCAND * NBT];
        for (int idx = t; idx < NCAND * NBT; idx += NTHR) {
            const int nn = idx / NBT;
            const int bt = idx - nn * NBT;
            float ssum = 0.0f;
            #pragma unroll
            for (int k = 0; k < SPLIT; k++)
                ssum += __ldcg(&g_partial[(nn * SPLIT + k) * NBT + bt]);
            ssum *= (1.0f / (float)(3 * NPIX));
            sadSh[idx] = ssum;
            out[idx] = ssum;
        }
        __syncthreads();
        if (t < NBT && out_size >= NCAND * NBT + 4 * NBT) {
            const int bt = t;
            float best = sadSh[bt];
            int bn = 0;
            for (int nn = 1; nn < NCAND; nn++) {
                const float v = sadSh[nn * NBT + bt];
                if (v < best) { best = v; bn = nn; }
            }
            const int a0 = bn / 15;
            const int a1 = (bn / 3) % 5;
            const int a2 = bn % 3;
            out[NCAND * NBT + 0 * NBT + bt] = (float)a0;
            out[NCAND * NBT + 1 * NBT + bt] = (float)a1;
            out[NCAND * NBT + 2 * NBT + bt] = (float)a2;
            out[NCAND * NBT + 3 * NBT + bt] = 0.0f;
        }
    }
}

extern "C" void kernel_launch(void* const* d_in, const int* in_sizes, int n_in,
                              void* d_out, int out_size) {
    const float* matrix = (const float*)d_in[0];
    const float* refm   = (const float*)d_in[1];

    convert_kernel<<<IMG_BLKS + REF_BLKS, 256>>>(matrix, refm);

    dim3 grid(NCAND, SPLIT);
    sad_kernel<<<grid, NTHR>>>((float*)d_out, out_size);
}

// round 6
// speedup vs baseline: 2.5081x; 1.1316x over previous
#include <cuda_runtime.h>
#include <cuda_fp16.h>
#include <math.h>

#define H 192
#define W 192
#define HW (H*W)
#define NCH 24          // BT*C = 8*3
#define CROP 174
#define H0 9
#define W0 9
#define NPIX (CROP*CROP)        // 30276
#define NCAND 75
#define SPLIT 15        // 75*15 = 1125 blocks < 148*8 = 1184 -> single wave
#define NBT 8
#define NLANES 64       // pixel lanes per block
#define NTHR 192        // NLANES * 3 groups
#define IMG_BLKS (HW / 256)                 // 144
#define REF_BLKS ((NPIX + 255) / 256)       // 119

__device__ __half g_imgT[HW * NCH];           // [y][x][ch] fp16
__device__ __half g_refT[NPIX * NCH];         // [i][j][ch] fp16
__device__ float  g_partial[NCAND * SPLIT * NBT];
__device__ int    g_count;

// ---------------------------------------------------------------------------
// Convert+transpose via smem tiles: coalesced channel-row reads, coalesced
// 4B record writes. Blocks [0,144) do the image, [144,263) the ref crop.
// Also resets the completion counter used by the fused finalize.
// ---------------------------------------------------------------------------
__global__ __launch_bounds__(256) void convert_kernel(const float* __restrict__ img,
                                                      const float* __restrict__ ref) {
    __shared__ __half s[256][26];   // stride 26 halves = 52 B (4-aligned)
    const int b = blockIdx.x;
    const int tid = threadIdx.x;
    if (b == 0 && tid == 0) g_count = 0;

    if (b < IMG_BLKS) {
        const int p0 = b * 256;
        #pragma unroll
        for (int ch = 0; ch < NCH; ch++)
            s[tid][ch] = __float2half(img[ch * HW + p0 + tid]);
        __syncthreads();
        unsigned int* out32 = (unsigned int*)g_imgT;
        #pragma unroll
        for (int w = 0; w < 12; w++) {
            const int idx = w * 256 + tid;       // 0..3071
            const int px = idx / 12;
            const int u  = idx - px * 12;
            out32[p0 * 12 + idx] = *(const unsigned int*)&s[px][2 * u];
        }
    } else {
        const int p0 = (b - IMG_BLKS) * 256;
        const int p = p0 + tid;
        const bool valid = (p < NPIX);
        const int i = p / CROP;
        const int j = p - i * CROP;
        const int src = (i + H0) * W + (j + W0);
        #pragma unroll
        for (int ch = 0; ch < NCH; ch++)
            s[tid][ch] = valid ? __float2half(ref[ch * HW + src]) : __half(0.0f);
        __syncthreads();
        const int total32 = (min(256, NPIX - p0)) * 12;
        unsigned int* out32 = (unsigned int*)g_refT;
        #pragma unroll
        for (int w = 0; w < 12; w++) {
            const int idx = w * 256 + tid;
            if (idx < total32) {
                const int px = idx / 12;
                const int u  = idx - px * 12;
                out32[p0 * 12 + idx] = *(const unsigned int*)&s[px][2 * u];
            }
        }
    }
}

// ---------------------------------------------------------------------------
// Main SAD kernel (fp16 data, half2 math) + fused finalize (last block).
// Block = 192 threads = 64 pixel-lanes x 3 channel-groups (8 ch each).
// Grid  = (NCAND, SPLIT) = 1125 blocks -> single wave at 8 blocks/SM.
// All corners provably in-bounds (9px margin vs <4.3px max displacement)
// -> no masks/clamps. Coordinates affine in (i,j).
// ---------------------------------------------------------------------------
__global__ __launch_bounds__(NTHR, 8) void sad_kernel(float* __restrict__ out,
                                                      int out_size) {
    const int n = blockIdx.x;
    const int s = blockIdx.y;
    const int t = threadIdx.x;
    const int g = t % 3;          // channel group: ch = 8g .. 8g+7
    const int lane_px = t / 3;    // 0..63
    const int g8 = 8 * g;

    // Candidate parameters: n = i0*15 + i1*3 + i2  (DIMS 5,5,3,1)
    const int i0 = n / 15;
    const int i1 = (n / 3) % 5;
    const int i2 = n % 3;
    const float ash = (float)(2 - i0);
    const float asw = (float)(2 - i1);
    const float arot = -(float)(i2 - 1) * (float)(M_PI / 180.0);
    const float cr = cosf(arot);
    const float sr = sinf(arot);

    // Affine map: x = ax*j + bx*i + cx0 ; y = ay*j + by*i + cy0
    const float SC = 96.0f / 95.5f;
    const float u0 = asw - 86.5f;
    const float v0 = ash - 86.5f;
    const float ax = SC * cr;
    const float bx = -SC * sr;
    const float cx0 = SC * (cr * u0 - sr * v0) + 95.5f;
    const float ay = SC * sr;
    const float by = SC * cr;
    const float cy0 = SC * (sr * u0 + cr * v0) + 95.5f;

    float acc[8];
    #pragma unroll
    for (int k = 0; k < 8; k++) acc[k] = 0.0f;

    const int chunk = (NPIX + SPLIT - 1) / SPLIT;
    const int p_begin = s * chunk;
    const int p_end   = min(p_begin + chunk, NPIX);

    // Incremental (i, j): stride 64 < CROP so at most one row wrap per step.
    int p = p_begin + lane_px;
    int pi = p / CROP;
    int pj = p - pi * CROP;

    #pragma unroll 2
    for (; p < p_end; p += NLANES) {
        const float x = fmaf(ax, (float)pj, fmaf(bx, (float)pi, cx0));
        const float y = fmaf(ay, (float)pj, fmaf(by, (float)pi, cy0));

        const float x0f = floorf(x);
        const float y0f = floorf(y);
        const float wx = x - x0f;
        const float wy = y - y0f;
        const int x0 = (int)x0f;
        const int y0 = (int)y0f;

        const float wx1 = 1.0f - wx;
        const float wy1 = 1.0f - wy;
        const __half2 wA2 = __float2half2_rn(wx1 * wy1);
        const __half2 wB2 = __float2half2_rn(wx  * wy1);
        const __half2 wC2 = __float2half2_rn(wx1 * wy);
        const __half2 wD2 = __float2half2_rn(wx  * wy);

        const int base = (y0 * W + x0) * NCH + g8;

        const float4 fA = *(const float4*)(g_imgT + base);
        const float4 fB = *(const float4*)(g_imgT + base + NCH);
        const float4 fC = *(const float4*)(g_imgT + base + W * NCH);
        const float4 fD = *(const float4*)(g_imgT + base + W * NCH + NCH);
        const float4 fR = *(const float4*)(g_refT + p * NCH + g8);

        const __half2* hA = (const __half2*)&fA;
        const __half2* hB = (const __half2*)&fB;
        const __half2* hC = (const __half2*)&fC;
        const __half2* hD = (const __half2*)&fD;
        const __half2* hR = (const __half2*)&fR;

        #pragma unroll
        for (int u = 0; u < 4; u++) {
            __half2 tv = __hmul2(wA2, hA[u]);
            tv = __hfma2(wB2, hB[u], tv);
            tv = __hfma2(wC2, hC[u], tv);
            tv = __hfma2(wD2, hD[u], tv);
            const __half2 d = __habs2(__hsub2(tv, hR[u]));
            const float2 df = __half22float2(d);
            acc[2 * u]     += df.x;
            acc[2 * u + 1] += df.y;
        }

        pj += NLANES;
        if (pj >= CROP) { pj -= CROP; pi += 1; }
    }

    // ---- Deterministic block reduction ----
    __shared__ float sc[8 * NTHR];
    __shared__ float s2[NBT * 24];
    #pragma unroll
    for (int k = 0; k < 8; k++) sc[k * NTHR + t] = acc[k];
    __syncthreads();
    {
        const int bt = t / 24;
        const int ii = t % 24;
        const int c  = bt * 3 + ii / 8;
        const int gs = c / 8;
        const int k  = c % 8;
        const int m8 = ii % 8;
        float ssum = 0.0f;
        #pragma unroll
        for (int jj = 0; jj < 8; jj++)
            ssum += sc[k * NTHR + gs + 3 * (m8 * 8 + jj)];
        s2[bt * 24 + ii] = ssum;
    }
    __syncthreads();
    if (t < NBT) {
        float ssum = 0.0f;
        #pragma unroll
        for (int ii = 0; ii < 24; ii++)
            ssum += s2[t * 24 + ii];
        g_partial[(n * SPLIT + s) * NBT + t] = ssum;
    }

    // ---- Fused finalize: last block to finish does the reduction ----
    __shared__ int isLast;
    __threadfence();
    __syncthreads();
    if (t == 0) {
        const int old = atomicAdd(&g_count, 1);
        isLast = (old == NCAND * SPLIT - 1) ? 1 : 0;
    }
    __syncthreads();
    if (isLast) {
        __shared__ float sadSh[NCAND * NBT];
        for (int idx = t; idx < NCAND * NBT; idx += NTHR) {
            const int nn = idx / NBT;
            const int bt = idx - nn * NBT;
            float ssum = 0.0f;
            #pragma unroll
            for (int k = 0; k < SPLIT; k++)
                ssum += __ldcg(&g_partial[(nn * SPLIT + k) * NBT + bt]);
            ssum *= (1.0f / (float)(3 * NPIX));
            sadSh[idx] = ssum;
            out[idx] = ssum;
        }
        __syncthreads();
        if (t < NBT && out_size >= NCAND * NBT + 4 * NBT) {
            const int bt = t;
            float best = sadSh[bt];
            int bn = 0;
            for (int nn = 1; nn < NCAND; nn++) {
                const float v = sadSh[nn * NBT + bt];
                if (v < best) { best = v; bn = nn; }
            }
            const int a0 = bn / 15;
            const int a1 = (bn / 3) % 5;
            const int a2 = bn % 3;
            out[NCAND * NBT + 0 * NBT + bt] = (float)a0;
            out[NCAND * NBT + 1 * NBT + bt] = (float)a1;
            out[NCAND * NBT + 2 * NBT + bt] = (float)a2;
            out[NCAND * NBT + 3 * NBT + bt] = 0.0f;
        }
    }
}

extern "C" void kernel_launch(void* const* d_in, const int* in_sizes, int n_in,
                              void* d_out, int out_size) {
    const float* matrix = (const float*)d_in[0];
    const float* refm   = (const float*)d_in[1];

    convert_kernel<<<IMG_BLKS + REF_BLKS, 256>>>(matrix, refm);

    dim3 grid(NCAND, SPLIT);
    sad_kernel<<<grid, NTHR>>>((float*)d_out, out_size);
}